// round 16
// baseline (speedup 1.0000x reference)
#include <cuda_runtime.h>

#define D 64
#define NMAX 150016
#define EMAX 4800000
#define LMAX 3
#define NBMAX 1024   // max scan blocks (NMAX/256 = 587)

// Scratch (device globals: allocation-free per harness rules)
__device__ unsigned int g_egoh[NMAX * 32];        // bf16x2 embeddings
__device__ float g_side[NMAX * D];                // SpMM result
__device__ float g_all[NMAX * (LMAX + 1) * D];    // concat of [ego0, norm1, norm2, norm3]
__device__ int   g_cnt[NMAX];                     // per-row edge counts (re-zeroed each pass)
__device__ int   g_rowptr[NMAX + 1];              // CSR row pointers
__device__ int   g_rowcur[NMAX];                  // scatter cursors
__device__ int2  g_edge[EMAX];                    // (val bits, col) sorted by row
__device__ int   g_bsum[NBMAX];                   // per-block count sums
__device__ int   g_boff[NBMAX];                   // exclusive block offsets
__device__ int   g_dbin[256];                     // degree histogram (re-zeroed each pass)
__device__ int   g_dcur[256];                     // degree-bucket cursors
__device__ int   g_rowperm[NMAX];                 // rows sorted by degree

// ---- packed f32x2 helpers ---------------------------------------------------
__device__ __forceinline__ void ffma2(unsigned long long& d,
                                      unsigned long long a,
                                      unsigned long long b) {
    asm("fma.rn.f32x2 %0, %1, %2, %0;" : "+l"(d) : "l"(a), "l"(b));
}
__device__ __forceinline__ unsigned long long pack2(float lo, float hi) {
    unsigned long long r;
    asm("mov.b64 %0, {%1, %2};" : "=l"(r) : "f"(lo), "f"(hi));
    return r;
}
__device__ __forceinline__ float2 unpack2(unsigned long long v) {
    float2 r;
    asm("mov.b64 {%0, %1}, %2;" : "=f"(r.x), "=f"(r.y) : "l"(v));
    return r;
}
// fp32 -> bf16 round-to-nearest-even, pure bit ops
__device__ __forceinline__ unsigned int f2bf_rn(float f) {
    unsigned int x = __float_as_uint(f);
    return (x + 0x7FFFu + ((x >> 16) & 1u)) >> 16;
}
__device__ __forceinline__ unsigned int packbf2(float lo, float hi) {
    return f2bf_rn(lo) | (f2bf_rn(hi) << 16);
}
__device__ __forceinline__ float bf_lo(unsigned int u) { return __uint_as_float(u << 16); }
__device__ __forceinline__ float bf_hi(unsigned int u) { return __uint_as_float(u & 0xFFFF0000u); }

// 32B gather with L2 evict_last (ego table stays L2-resident)
__device__ __forceinline__ void ldg_ego8(const unsigned int* p, unsigned int* r) {
    asm volatile("ld.global.nc.L2::evict_last.v8.b32 {%0,%1,%2,%3,%4,%5,%6,%7}, [%8];"
                 : "=r"(r[0]), "=r"(r[1]), "=r"(r[2]), "=r"(r[3]),
                   "=r"(r[4]), "=r"(r[5]), "=r"(r[6]), "=r"(r[7])
                 : "l"(p));
}

// ---------------------------------------------------------------------------
// init+hist fused
// ---------------------------------------------------------------------------
__global__ void init_hist_kernel(const float* __restrict__ ue,
                                 const float* __restrict__ ie,
                                 const int* __restrict__ arow,
                                 int n_user, int n, int E) {
    int tid = blockIdx.x * blockDim.x + threadIdx.x;

    int total = n * (D / 4);
    if (tid < total) {
        int row = tid >> 4;
        int q4 = tid & 15;
        float4 v;
        if (row < n_user) v = *(const float4*)(ue + row * D + q4 * 4);
        else              v = *(const float4*)(ie + (row - n_user) * D + q4 * 4);
        *(float4*)&g_all[row * ((LMAX + 1) * D) + q4 * 4] = v;
        g_egoh[row * 32 + q4 * 2 + 0] = packbf2(v.x, v.y);
        g_egoh[row * 32 + q4 * 2 + 1] = packbf2(v.z, v.w);
    }

    int e = tid * 4;
    if (e + 4 <= E) {
        int4 r4 = *(const int4*)(arow + e);
        atomicAdd(&g_cnt[r4.x], 1);
        atomicAdd(&g_cnt[r4.y], 1);
        atomicAdd(&g_cnt[r4.z], 1);
        atomicAdd(&g_cnt[r4.w], 1);
    } else {
        for (int k = e; k < E; k++) atomicAdd(&g_cnt[__ldg(arow + k)], 1);
    }
}

// ---------------------------------------------------------------------------
// CSR step 2a: per-block sums of counts
// ---------------------------------------------------------------------------
__global__ void bsum_kernel(int n) {
    __shared__ int s[8];
    int i = blockIdx.x * 256 + threadIdx.x;
    int v = (i < n) ? g_cnt[i] : 0;
#pragma unroll
    for (int off = 16; off > 0; off >>= 1)
        v += __shfl_down_sync(0xffffffffu, v, off);
    if ((threadIdx.x & 31) == 0) s[threadIdx.x >> 5] = v;
    __syncthreads();
    if (threadIdx.x < 8) {
        int x = s[threadIdx.x];
#pragma unroll
        for (int off = 4; off > 0; off >>= 1)
            x += __shfl_down_sync(0xffu, x, off, 8);
        if (threadIdx.x == 0) g_bsum[blockIdx.x] = x;
    }
}

// ---------------------------------------------------------------------------
// CSR step 2b: single-block exclusive scan of block sums
// ---------------------------------------------------------------------------
__global__ void bscan_kernel(int nb) {
    __shared__ int s[NBMAX];
    int t = threadIdx.x;
    int v = (t < nb) ? g_bsum[t] : 0;
    s[t] = v;
    __syncthreads();
    for (int off = 1; off < NBMAX; off <<= 1) {
        int x = (t >= off) ? s[t - off] : 0;
        __syncthreads();
        s[t] += x;
        __syncthreads();
    }
    if (t < nb) g_boff[t] = s[t] - v;
}

// ---------------------------------------------------------------------------
// CSR step 2c: per-block scan + offset -> rowptr, rowcur; re-zero cnt;
// also histogram degrees into 256 bins for the counting sort.
// ---------------------------------------------------------------------------
__global__ void rowptr_kernel(int n, int E) {
    __shared__ int s[256];
    int t = threadIdx.x;
    int i = blockIdx.x * 256 + t;
    int v = (i < n) ? g_cnt[i] : 0;
    s[t] = v;
    __syncthreads();
    for (int off = 1; off < 256; off <<= 1) {
        int x = (t >= off) ? s[t - off] : 0;
        __syncthreads();
        s[t] += x;
        __syncthreads();
    }
    if (i < n) {
        int p = g_boff[blockIdx.x] + s[t] - v;
        g_rowptr[i] = p;
        g_rowcur[i] = p;
        g_cnt[i] = 0;
        atomicAdd(&g_dbin[v > 255 ? 255 : v], 1);
    }
    if (i == 0) g_rowptr[n] = E;
}

// ---------------------------------------------------------------------------
// Degree-bucket scan: exclusive prefix of 256 bins -> cursors; re-zero bins
// ---------------------------------------------------------------------------
__global__ void dscan_kernel() {
    __shared__ int s[256];
    int t = threadIdx.x;
    int v = g_dbin[t];
    s[t] = v;
    __syncthreads();
    for (int off = 1; off < 256; off <<= 1) {
        int x = (t >= off) ? s[t - off] : 0;
        __syncthreads();
        s[t] += x;
        __syncthreads();
    }
    g_dcur[t] = s[t] - v;
    g_dbin[t] = 0;           // ready for next replay
}

// ---------------------------------------------------------------------------
// Permute rows by degree (counting-sort scatter)
// ---------------------------------------------------------------------------
__global__ void dperm_kernel(int n) {
    int i = blockIdx.x * blockDim.x + threadIdx.x;
    if (i >= n) return;
    int deg = g_rowptr[i + 1] - g_rowptr[i];
    if (deg > 255) deg = 255;
    int pos = atomicAdd(&g_dcur[deg], 1);
    g_rowperm[pos] = i;
}

// ---------------------------------------------------------------------------
// CSR step 3: scatter edges into row-sorted order (4 edges per thread)
// ---------------------------------------------------------------------------
__global__ void scatter_kernel(const float* __restrict__ aval,
                               const int* __restrict__ arow,
                               const int* __restrict__ acol, int E) {
    int e = (blockIdx.x * blockDim.x + threadIdx.x) * 4;
    if (e + 4 <= E) {
        int4   r4 = *(const int4*)(arow + e);
        int4   c4 = *(const int4*)(acol + e);
        float4 v4 = *(const float4*)(aval + e);
        int p0 = atomicAdd(&g_rowcur[r4.x], 1);
        int p1 = atomicAdd(&g_rowcur[r4.y], 1);
        int p2 = atomicAdd(&g_rowcur[r4.z], 1);
        int p3 = atomicAdd(&g_rowcur[r4.w], 1);
        g_edge[p0] = make_int2(__float_as_int(v4.x), c4.x);
        g_edge[p1] = make_int2(__float_as_int(v4.y), c4.y);
        g_edge[p2] = make_int2(__float_as_int(v4.z), c4.z);
        g_edge[p3] = make_int2(__float_as_int(v4.w), c4.w);
    } else {
        for (int k = e; k < E; k++) {
            int r = __ldg(arow + k);
            int p = atomicAdd(&g_rowcur[r], 1);
            g_edge[p] = make_int2(__float_as_int(__ldg(aval + k)), __ldg(acol + k));
        }
    }
}

// ---------------------------------------------------------------------------
// SpMM (CSR, bf16 gather, fp32 accumulate): 4 lanes per row, 32B per lane,
// rows processed in degree-sorted order (uniform warp loop counts).
// ---------------------------------------------------------------------------
__device__ __forceinline__ void bf16_fma16(float* acc, const unsigned int* u, float v) {
#pragma unroll
    for (int i = 0; i < 8; i++) {
        acc[2 * i + 0] += v * bf_lo(u[i]);
        acc[2 * i + 1] += v * bf_hi(u[i]);
    }
}

__global__ void __launch_bounds__(256)
spmm_csr_kernel(int n) {
    int t = threadIdx.x;
    int lane = t & 3;                    // 4 lanes per row
    int idx = blockIdx.x * 64 + (t >> 2);
    if (idx >= n) return;
    int row = __ldg(&g_rowperm[idx]);

    int start = __ldg(&g_rowptr[row]);
    int end   = __ldg(&g_rowptr[row + 1]);

    const unsigned int* base = g_egoh + lane * 8;   // this lane's 32B slice
    float acc[16];
#pragma unroll
    for (int i = 0; i < 16; i++) acc[i] = 0.f;

    int j = start;
    if (j + 4 <= end) {
        int2 e0 = __ldg(&g_edge[j + 0]);
        int2 e1 = __ldg(&g_edge[j + 1]);
        int2 e2 = __ldg(&g_edge[j + 2]);
        int2 e3 = __ldg(&g_edge[j + 3]);
        for (; j + 8 <= end; j += 4) {
            int2 f0 = __ldg(&g_edge[j + 4]);
            int2 f1 = __ldg(&g_edge[j + 5]);
            int2 f2 = __ldg(&g_edge[j + 6]);
            int2 f3 = __ldg(&g_edge[j + 7]);
            unsigned int x0[8], x1[8], x2[8], x3[8];
            ldg_ego8(base + e0.y * 32, x0);
            ldg_ego8(base + e1.y * 32, x1);
            ldg_ego8(base + e2.y * 32, x2);
            ldg_ego8(base + e3.y * 32, x3);
            bf16_fma16(acc, x0, __int_as_float(e0.x));
            bf16_fma16(acc, x1, __int_as_float(e1.x));
            bf16_fma16(acc, x2, __int_as_float(e2.x));
            bf16_fma16(acc, x3, __int_as_float(e3.x));
            e0 = f0; e1 = f1; e2 = f2; e3 = f3;
        }
        {
            unsigned int x0[8], x1[8], x2[8], x3[8];
            ldg_ego8(base + e0.y * 32, x0);
            ldg_ego8(base + e1.y * 32, x1);
            ldg_ego8(base + e2.y * 32, x2);
            ldg_ego8(base + e3.y * 32, x3);
            bf16_fma16(acc, x0, __int_as_float(e0.x));
            bf16_fma16(acc, x1, __int_as_float(e1.x));
            bf16_fma16(acc, x2, __int_as_float(e2.x));
            bf16_fma16(acc, x3, __int_as_float(e3.x));
            j += 4;
        }
    }
    for (; j < end; j++) {
        int2 e = __ldg(&g_edge[j]);
        unsigned int x[8];
        ldg_ego8(base + e.y * 32, x);
        bf16_fma16(acc, x, __int_as_float(e.x));
    }

    float4* dst = (float4*)&g_side[row * D + lane * 16];
#pragma unroll
    for (int k = 0; k < 4; k++)
        dst[k] = make_float4(acc[4 * k], acc[4 * k + 1], acc[4 * k + 2], acc[4 * k + 3]);
}

// ---------------------------------------------------------------------------
// Dense: ego_new = leaky(side@Wgc + bgc + (ego*side)@Wbi + bbi)
//        all[:, (k+1)*64:] = l2norm(ego_new); egoh = bf16(ego_new) if !last
// ---------------------------------------------------------------------------
__global__ void __launch_bounds__(256, 1)
dense_kernel(const float* __restrict__ Wgc, const float* __restrict__ bgc,
             const float* __restrict__ Wbi, const float* __restrict__ bbi,
             int n, int layer, int write_mirror) {
    __shared__ float s_s[16][68];
    __shared__ float s_p[16][68];
    __shared__ float s_o[16][68];
    __shared__ float s_rn[16];

    int t = threadIdx.x;
    int j = t & 63;
    int rg = t >> 6;
    int row00 = blockIdx.x * 64;

    unsigned long long wgp[32], wbp[32];
#pragma unroll
    for (int k2 = 0; k2 < 32; k2++) {
        wgp[k2] = pack2(__ldg(Wgc + (2 * k2) * 64 + j), __ldg(Wgc + (2 * k2 + 1) * 64 + j));
        wbp[k2] = pack2(__ldg(Wbi + (2 * k2) * 64 + j), __ldg(Wbi + (2 * k2 + 1) * 64 + j));
    }
    float bias = __ldg(bgc + j) + __ldg(bbi + j);

    for (int sub = 0; sub < 4; sub++) {
        int row0 = row00 + sub * 16;
        {
            int base = t * 4;
            int r = base >> 6;
            int c = base & 63;
            int grow = row0 + r;
            float4 sv = make_float4(0.f, 0.f, 0.f, 0.f);
            float4 ev = sv;
            if (grow < n) {
                sv = *(const float4*)&g_side[grow * D + c];
                uint2 em = ((const uint2*)g_egoh)[grow * 16 + (c >> 2)];
                ev = make_float4(bf_lo(em.x), bf_hi(em.x), bf_lo(em.y), bf_hi(em.y));
            }
            *(float4*)&s_s[r][c] = sv;
            float4 pv = make_float4(sv.x * ev.x, sv.y * ev.y, sv.z * ev.z, sv.w * ev.w);
            *(float4*)&s_p[r][c] = pv;
        }
        __syncthreads();

        unsigned long long acc01[4], acc23[4];
#pragma unroll
        for (int rr = 0; rr < 4; rr++) { acc01[rr] = 0ULL; acc23[rr] = 0ULL; }

#pragma unroll
        for (int k4 = 0; k4 < 16; k4++) {
#pragma unroll
            for (int rr = 0; rr < 4; rr++) {
                int r = rg * 4 + rr;
                ulonglong2 s2 = *(const ulonglong2*)&s_s[r][k4 * 4];
                ulonglong2 p2 = *(const ulonglong2*)&s_p[r][k4 * 4];
                ffma2(acc01[rr], s2.x, wgp[2 * k4 + 0]);
                ffma2(acc23[rr], s2.y, wgp[2 * k4 + 1]);
                ffma2(acc01[rr], p2.x, wbp[2 * k4 + 0]);
                ffma2(acc23[rr], p2.y, wbp[2 * k4 + 1]);
            }
        }

        float aout[4];
#pragma unroll
        for (int rr = 0; rr < 4; rr++) {
            int r = rg * 4 + rr;
            float2 u = unpack2(acc01[rr]);
            float2 w = unpack2(acc23[rr]);
            float a = bias + ((u.x + u.y) + (w.x + w.y));
            a = (a > 0.f) ? a : 0.2f * a;     // leaky_relu(0.2)
            aout[rr] = a;
            s_o[r][j] = a;
        }
        __syncthreads();

        {
            int r = t >> 4;
            int i = t & 15;
            float ss = 0.f;
#pragma unroll
            for (int q = 0; q < 4; q++) {
                float x = s_o[r][i + 16 * q];
                ss += x * x;
            }
#pragma unroll
            for (int off = 8; off > 0; off >>= 1)
                ss += __shfl_down_sync(0xffffffffu, ss, off, 16);
            if (i == 0) s_rn[r] = 1.f / fmaxf(sqrtf(ss), 1e-12f);
        }
        __syncthreads();

#pragma unroll
        for (int rr = 0; rr < 4; rr++) {
            int r = rg * 4 + rr;
            int grow = row0 + r;
            if (grow < n)
                g_all[grow * ((LMAX + 1) * D) + (layer + 1) * D + j] = aout[rr] * s_rn[r];
        }
        if (write_mirror) {
#pragma unroll
            for (int w = 0; w < 2; w++) {
                int u = t + w * 256;
                int r = u >> 5;
                int c = u & 31;
                int grow = row0 + r;
                if (grow < n)
                    g_egoh[grow * 32 + c] = packbf2(s_o[r][2 * c], s_o[r][2 * c + 1]);
            }
        }
        __syncthreads();
    }
}

// ---------------------------------------------------------------------------
// Gather: out[0:B*256) = all[users], out[B*256:2B*256) = all[N_USER+items]
// ---------------------------------------------------------------------------
__global__ void gather_kernel(const int* __restrict__ users,
                              const int* __restrict__ items,
                              float* __restrict__ out,
                              int B, int n_user) {
    int i = blockIdx.x * blockDim.x + threadIdx.x;
    const int stride = (LMAX + 1) * D / 4;
    int total = 2 * B * stride;
    if (i >= total) return;
    int which = (i >= B * stride) ? 1 : 0;
    int ii = i - which * B * stride;
    int b = ii >> 6;
    int q = ii & 63;
    int row = which ? (n_user + __ldg(items + b)) : __ldg(users + b);
    ((float4*)out)[i] = *(const float4*)&g_all[row * ((LMAX + 1) * D) + q * 4];
}

// ---------------------------------------------------------------------------
extern "C" void kernel_launch(void* const* d_in, const int* in_sizes, int n_in,
                              void* d_out, int out_size) {
    const float* ue   = (const float*)d_in[0];
    const float* ie   = (const float*)d_in[1];
    const float* Wgc  = (const float*)d_in[2];
    const float* bgc  = (const float*)d_in[3];
    const float* Wbi  = (const float*)d_in[4];
    const float* bbi  = (const float*)d_in[5];
    const float* aval = (const float*)d_in[6];
    const int*   arow = (const int*)d_in[7];
    const int*   acol = (const int*)d_in[8];
    const int*   users = (const int*)d_in[9];
    const int*   items = (const int*)d_in[10];

    int n_user = in_sizes[0] / D;
    int n_item = in_sizes[1] / D;
    int n = n_user + n_item;
    int E = in_sizes[6];
    int B = in_sizes[9];
    int L = in_sizes[3] / D;
    if (L > LMAX) L = LMAX;

    {
        int init_items = n * (D / 4);
        int hist_threads = (E + 3) / 4;
        int threads = init_items > hist_threads ? init_items : hist_threads;
        init_hist_kernel<<<(threads + 255) / 256, 256>>>(ue, ie, arow, n_user, n, E);
    }

    int nb = (n + 255) / 256;
    bsum_kernel<<<nb, 256>>>(n);
    bscan_kernel<<<1, NBMAX>>>(nb);
    rowptr_kernel<<<nb, 256>>>(n, E);
    dscan_kernel<<<1, 256>>>();
    dperm_kernel<<<nb, 256>>>(n);
    scatter_kernel<<<(E / 4 + 255) / 256 + 1, 256>>>(aval, arow, acol, E);

    for (int k = 0; k < L; k++) {
        spmm_csr_kernel<<<(n + 63) / 64, 256>>>(n);
        dense_kernel<<<(n + 63) / 64, 256>>>(Wgc + k * D * D, bgc + k * D,
                                             Wbi + k * D * D, bbi + k * D,
                                             n, k, k < L - 1 ? 1 : 0);
    }

    {
        int total = 2 * B * ((LMAX + 1) * D / 4);
        gather_kernel<<<(total + 255) / 256, 256>>>(users, items, (float*)d_out, B, n_user);
    }
}

// round 17
// speedup vs baseline: 1.0662x; 1.0662x over previous
#include <cuda_runtime.h>

#define D 64
#define NMAX 150016
#define EMAX 4800000
#define LMAX 3
#define NBMAX 1024   // max scan blocks (NMAX/256 = 587)

// Scratch (device globals: allocation-free per harness rules)
__device__ unsigned int g_egoh[NMAX * 32];        // bf16x2 embeddings (spmm gather + dense p input)
__device__ float g_side[NMAX * D];                // SpMM result
__device__ float g_all[NMAX * (LMAX + 1) * D];    // concat of [ego0, norm1, norm2, norm3]
__device__ int   g_cnt[NMAX];                     // per-row edge counts (zeroed by rowptr_kernel each pass)
__device__ int   g_rowptr[NMAX + 1];              // CSR row pointers
__device__ int   g_rowcur[NMAX];                  // scatter cursors
__device__ int2  g_edge[EMAX];                    // (val bits, col) sorted by row
__device__ int   g_bsum[NBMAX];                   // per-block count sums
__device__ int   g_boff[NBMAX];                   // exclusive block offsets

// ---- packed f32x2 helpers ---------------------------------------------------
__device__ __forceinline__ void ffma2(unsigned long long& d,
                                      unsigned long long a,
                                      unsigned long long b) {
    asm("fma.rn.f32x2 %0, %1, %2, %0;" : "+l"(d) : "l"(a), "l"(b));
}
__device__ __forceinline__ unsigned long long pack2(float lo, float hi) {
    unsigned long long r;
    asm("mov.b64 %0, {%1, %2};" : "=l"(r) : "f"(lo), "f"(hi));
    return r;
}
__device__ __forceinline__ float2 unpack2(unsigned long long v) {
    float2 r;
    asm("mov.b64 {%0, %1}, %2;" : "=f"(r.x), "=f"(r.y) : "l"(v));
    return r;
}
// fp32 -> bf16 round-to-nearest-even, pure bit ops
__device__ __forceinline__ unsigned int f2bf_rn(float f) {
    unsigned int x = __float_as_uint(f);
    return (x + 0x7FFFu + ((x >> 16) & 1u)) >> 16;
}
__device__ __forceinline__ unsigned int packbf2(float lo, float hi) {
    return f2bf_rn(lo) | (f2bf_rn(hi) << 16);
}
__device__ __forceinline__ float bf_lo(unsigned int u) { return __uint_as_float(u << 16); }
__device__ __forceinline__ float bf_hi(unsigned int u) { return __uint_as_float(u & 0xFFFF0000u); }

// 32B gather with L2 evict_last (keeps the ego table L2-resident against the
// evict-normal edge/side streams). .v8.b32 is the form ptxas requires.
__device__ __forceinline__ void ldg_ego8(const unsigned int* p, unsigned int* r) {
    asm volatile("ld.global.nc.L2::evict_last.v8.b32 {%0,%1,%2,%3,%4,%5,%6,%7}, [%8];"
                 : "=r"(r[0]), "=r"(r[1]), "=r"(r[2]), "=r"(r[3]),
                   "=r"(r[4]), "=r"(r[5]), "=r"(r[6]), "=r"(r[7])
                 : "l"(p));
}

// ---------------------------------------------------------------------------
// init+hist fused
// ---------------------------------------------------------------------------
__global__ void init_hist_kernel(const float* __restrict__ ue,
                                 const float* __restrict__ ie,
                                 const int* __restrict__ arow,
                                 int n_user, int n, int E) {
    int tid = blockIdx.x * blockDim.x + threadIdx.x;

    int total = n * (D / 4);
    if (tid < total) {
        int row = tid >> 4;
        int q4 = tid & 15;
        float4 v;
        if (row < n_user) v = *(const float4*)(ue + row * D + q4 * 4);
        else              v = *(const float4*)(ie + (row - n_user) * D + q4 * 4);
        *(float4*)&g_all[row * ((LMAX + 1) * D) + q4 * 4] = v;
        g_egoh[row * 32 + q4 * 2 + 0] = packbf2(v.x, v.y);
        g_egoh[row * 32 + q4 * 2 + 1] = packbf2(v.z, v.w);
    }

    int e = tid * 4;
    if (e + 4 <= E) {
        int4 r4 = *(const int4*)(arow + e);
        atomicAdd(&g_cnt[r4.x], 1);
        atomicAdd(&g_cnt[r4.y], 1);
        atomicAdd(&g_cnt[r4.z], 1);
        atomicAdd(&g_cnt[r4.w], 1);
    } else {
        for (int k = e; k < E; k++) atomicAdd(&g_cnt[__ldg(arow + k)], 1);
    }
}

// ---------------------------------------------------------------------------
// CSR step 2a: per-block sums of counts
// ---------------------------------------------------------------------------
__global__ void bsum_kernel(int n) {
    __shared__ int s[8];
    int i = blockIdx.x * 256 + threadIdx.x;
    int v = (i < n) ? g_cnt[i] : 0;
#pragma unroll
    for (int off = 16; off > 0; off >>= 1)
        v += __shfl_down_sync(0xffffffffu, v, off);
    if ((threadIdx.x & 31) == 0) s[threadIdx.x >> 5] = v;
    __syncthreads();
    if (threadIdx.x < 8) {
        int x = s[threadIdx.x];
#pragma unroll
        for (int off = 4; off > 0; off >>= 1)
            x += __shfl_down_sync(0xffu, x, off, 8);
        if (threadIdx.x == 0) g_bsum[blockIdx.x] = x;
    }
}

// ---------------------------------------------------------------------------
// CSR step 2b: single-block exclusive scan of block sums
// ---------------------------------------------------------------------------
__global__ void bscan_kernel(int nb) {
    __shared__ int s[NBMAX];
    int t = threadIdx.x;
    int v = (t < nb) ? g_bsum[t] : 0;
    s[t] = v;
    __syncthreads();
    for (int off = 1; off < NBMAX; off <<= 1) {
        int x = (t >= off) ? s[t - off] : 0;
        __syncthreads();
        s[t] += x;
        __syncthreads();
    }
    if (t < nb) g_boff[t] = s[t] - v;
}

// ---------------------------------------------------------------------------
// CSR step 2c: per-block scan + offset -> rowptr, rowcur; re-zero cnt
// ---------------------------------------------------------------------------
__global__ void rowptr_kernel(int n, int E) {
    __shared__ int s[256];
    int t = threadIdx.x;
    int i = blockIdx.x * 256 + t;
    int v = (i < n) ? g_cnt[i] : 0;
    s[t] = v;
    __syncthreads();
    for (int off = 1; off < 256; off <<= 1) {
        int x = (t >= off) ? s[t - off] : 0;
        __syncthreads();
        s[t] += x;
        __syncthreads();
    }
    if (i < n) {
        int p = g_boff[blockIdx.x] + s[t] - v;
        g_rowptr[i] = p;
        g_rowcur[i] = p;
        g_cnt[i] = 0;
    }
    if (i == 0) g_rowptr[n] = E;
}

// ---------------------------------------------------------------------------
// CSR step 3: scatter edges into row-sorted order (4 edges per thread)
// ---------------------------------------------------------------------------
__global__ void scatter_kernel(const float* __restrict__ aval,
                               const int* __restrict__ arow,
                               const int* __restrict__ acol, int E) {
    int e = (blockIdx.x * blockDim.x + threadIdx.x) * 4;
    if (e + 4 <= E) {
        int4   r4 = *(const int4*)(arow + e);
        int4   c4 = *(const int4*)(acol + e);
        float4 v4 = *(const float4*)(aval + e);
        int p0 = atomicAdd(&g_rowcur[r4.x], 1);
        int p1 = atomicAdd(&g_rowcur[r4.y], 1);
        int p2 = atomicAdd(&g_rowcur[r4.z], 1);
        int p3 = atomicAdd(&g_rowcur[r4.w], 1);
        g_edge[p0] = make_int2(__float_as_int(v4.x), c4.x);
        g_edge[p1] = make_int2(__float_as_int(v4.y), c4.y);
        g_edge[p2] = make_int2(__float_as_int(v4.z), c4.z);
        g_edge[p3] = make_int2(__float_as_int(v4.w), c4.w);
    } else {
        for (int k = e; k < E; k++) {
            int r = __ldg(arow + k);
            int p = atomicAdd(&g_rowcur[r], 1);
            g_edge[p] = make_int2(__float_as_int(__ldg(aval + k)), __ldg(acol + k));
        }
    }
}

// ---------------------------------------------------------------------------
// SpMM (CSR, bf16 gather, fp32 accumulate): 4 lanes per row, 32B per lane
// via v8.b32 evict_last gathers; 4-edge batches with next-batch prefetch.
// ---------------------------------------------------------------------------
__device__ __forceinline__ void bf16_fma16(float* acc, const unsigned int* u, float v) {
#pragma unroll
    for (int i = 0; i < 8; i++) {
        acc[2 * i + 0] += v * bf_lo(u[i]);
        acc[2 * i + 1] += v * bf_hi(u[i]);
    }
}

__global__ void __launch_bounds__(256)
spmm_csr_kernel(int n) {
    int t = threadIdx.x;
    int lane = t & 3;                    // 4 lanes per row
    int row = blockIdx.x * 64 + (t >> 2);
    if (row >= n) return;

    int start = __ldg(&g_rowptr[row]);
    int end   = __ldg(&g_rowptr[row + 1]);

    const unsigned int* base = g_egoh + lane * 8;   // this lane's 32B slice
    float acc[16];
#pragma unroll
    for (int i = 0; i < 16; i++) acc[i] = 0.f;

    int j = start;
    if (j + 4 <= end) {
        int2 e0 = __ldg(&g_edge[j + 0]);
        int2 e1 = __ldg(&g_edge[j + 1]);
        int2 e2 = __ldg(&g_edge[j + 2]);
        int2 e3 = __ldg(&g_edge[j + 3]);
        for (; j + 8 <= end; j += 4) {
            int2 f0 = __ldg(&g_edge[j + 4]);
            int2 f1 = __ldg(&g_edge[j + 5]);
            int2 f2 = __ldg(&g_edge[j + 6]);
            int2 f3 = __ldg(&g_edge[j + 7]);
            unsigned int x0[8], x1[8], x2[8], x3[8];
            ldg_ego8(base + e0.y * 32, x0);
            ldg_ego8(base + e1.y * 32, x1);
            ldg_ego8(base + e2.y * 32, x2);
            ldg_ego8(base + e3.y * 32, x3);
            bf16_fma16(acc, x0, __int_as_float(e0.x));
            bf16_fma16(acc, x1, __int_as_float(e1.x));
            bf16_fma16(acc, x2, __int_as_float(e2.x));
            bf16_fma16(acc, x3, __int_as_float(e3.x));
            e0 = f0; e1 = f1; e2 = f2; e3 = f3;
        }
        {
            unsigned int x0[8], x1[8], x2[8], x3[8];
            ldg_ego8(base + e0.y * 32, x0);
            ldg_ego8(base + e1.y * 32, x1);
            ldg_ego8(base + e2.y * 32, x2);
            ldg_ego8(base + e3.y * 32, x3);
            bf16_fma16(acc, x0, __int_as_float(e0.x));
            bf16_fma16(acc, x1, __int_as_float(e1.x));
            bf16_fma16(acc, x2, __int_as_float(e2.x));
            bf16_fma16(acc, x3, __int_as_float(e3.x));
            j += 4;
        }
    }
    for (; j < end; j++) {
        int2 e = __ldg(&g_edge[j]);
        unsigned int x[8];
        ldg_ego8(base + e.y * 32, x);
        bf16_fma16(acc, x, __int_as_float(e.x));
    }

    float4* dst = (float4*)&g_side[row * D + lane * 16];
#pragma unroll
    for (int k = 0; k < 4; k++)
        dst[k] = make_float4(acc[4 * k], acc[4 * k + 1], acc[4 * k + 2], acc[4 * k + 3]);
}

// ---------------------------------------------------------------------------
// Dense: ego_new = leaky(side@Wgc + bgc + (ego*side)@Wbi + bbi)
//        all[:, (k+1)*64:] = l2norm(ego_new); egoh = bf16(ego_new) if !last
// ---------------------------------------------------------------------------
__global__ void __launch_bounds__(256, 1)
dense_kernel(const float* __restrict__ Wgc, const float* __restrict__ bgc,
             const float* __restrict__ Wbi, const float* __restrict__ bbi,
             int n, int layer, int write_mirror) {
    __shared__ float s_s[16][68];
    __shared__ float s_p[16][68];
    __shared__ float s_o[16][68];
    __shared__ float s_rn[16];

    int t = threadIdx.x;
    int j = t & 63;
    int rg = t >> 6;
    int row00 = blockIdx.x * 64;

    unsigned long long wgp[32], wbp[32];
#pragma unroll
    for (int k2 = 0; k2 < 32; k2++) {
        wgp[k2] = pack2(__ldg(Wgc + (2 * k2) * 64 + j), __ldg(Wgc + (2 * k2 + 1) * 64 + j));
        wbp[k2] = pack2(__ldg(Wbi + (2 * k2) * 64 + j), __ldg(Wbi + (2 * k2 + 1) * 64 + j));
    }
    float bias = __ldg(bgc + j) + __ldg(bbi + j);

    for (int sub = 0; sub < 4; sub++) {
        int row0 = row00 + sub * 16;
        {
            int base = t * 4;
            int r = base >> 6;
            int c = base & 63;
            int grow = row0 + r;
            float4 sv = make_float4(0.f, 0.f, 0.f, 0.f);
            float4 ev = sv;
            if (grow < n) {
                sv = *(const float4*)&g_side[grow * D + c];
                uint2 em = ((const uint2*)g_egoh)[grow * 16 + (c >> 2)];
                ev = make_float4(bf_lo(em.x), bf_hi(em.x), bf_lo(em.y), bf_hi(em.y));
            }
            *(float4*)&s_s[r][c] = sv;
            float4 pv = make_float4(sv.x * ev.x, sv.y * ev.y, sv.z * ev.z, sv.w * ev.w);
            *(float4*)&s_p[r][c] = pv;
        }
        __syncthreads();

        unsigned long long acc01[4], acc23[4];
#pragma unroll
        for (int rr = 0; rr < 4; rr++) { acc01[rr] = 0ULL; acc23[rr] = 0ULL; }

#pragma unroll
        for (int k4 = 0; k4 < 16; k4++) {
#pragma unroll
            for (int rr = 0; rr < 4; rr++) {
                int r = rg * 4 + rr;
                ulonglong2 s2 = *(const ulonglong2*)&s_s[r][k4 * 4];
                ulonglong2 p2 = *(const ulonglong2*)&s_p[r][k4 * 4];
                ffma2(acc01[rr], s2.x, wgp[2 * k4 + 0]);
                ffma2(acc23[rr], s2.y, wgp[2 * k4 + 1]);
                ffma2(acc01[rr], p2.x, wbp[2 * k4 + 0]);
                ffma2(acc23[rr], p2.y, wbp[2 * k4 + 1]);
            }
        }

        float aout[4];
#pragma unroll
        for (int rr = 0; rr < 4; rr++) {
            int r = rg * 4 + rr;
            float2 u = unpack2(acc01[rr]);
            float2 w = unpack2(acc23[rr]);
            float a = bias + ((u.x + u.y) + (w.x + w.y));
            a = (a > 0.f) ? a : 0.2f * a;     // leaky_relu(0.2)
            aout[rr] = a;
            s_o[r][j] = a;
        }
        __syncthreads();

        {
            int r = t >> 4;
            int i = t & 15;
            float ss = 0.f;
#pragma unroll
            for (int q = 0; q < 4; q++) {
                float x = s_o[r][i + 16 * q];
                ss += x * x;
            }
#pragma unroll
            for (int off = 8; off > 0; off >>= 1)
                ss += __shfl_down_sync(0xffffffffu, ss, off, 16);
            if (i == 0) s_rn[r] = 1.f / fmaxf(sqrtf(ss), 1e-12f);
        }
        __syncthreads();

#pragma unroll
        for (int rr = 0; rr < 4; rr++) {
            int r = rg * 4 + rr;
            int grow = row0 + r;
            if (grow < n)
                g_all[grow * ((LMAX + 1) * D) + (layer + 1) * D + j] = aout[rr] * s_rn[r];
        }
        if (write_mirror) {
#pragma unroll
            for (int w = 0; w < 2; w++) {
                int u = t + w * 256;
                int r = u >> 5;
                int c = u & 31;
                int grow = row0 + r;
                if (grow < n)
                    g_egoh[grow * 32 + c] = packbf2(s_o[r][2 * c], s_o[r][2 * c + 1]);
            }
        }
        __syncthreads();
    }
}

// ---------------------------------------------------------------------------
// Gather: out[0:B*256) = all[users], out[B*256:2B*256) = all[N_USER+items]
// ---------------------------------------------------------------------------
__global__ void gather_kernel(const int* __restrict__ users,
                              const int* __restrict__ items,
                              float* __restrict__ out,
                              int B, int n_user) {
    int i = blockIdx.x * blockDim.x + threadIdx.x;
    const int stride = (LMAX + 1) * D / 4;
    int total = 2 * B * stride;
    if (i >= total) return;
    int which = (i >= B * stride) ? 1 : 0;
    int ii = i - which * B * stride;
    int b = ii >> 6;
    int q = ii & 63;
    int row = which ? (n_user + __ldg(items + b)) : __ldg(users + b);
    ((float4*)out)[i] = *(const float4*)&g_all[row * ((LMAX + 1) * D) + q * 4];
}

// ---------------------------------------------------------------------------
extern "C" void kernel_launch(void* const* d_in, const int* in_sizes, int n_in,
                              void* d_out, int out_size) {
    const float* ue   = (const float*)d_in[0];
    const float* ie   = (const float*)d_in[1];
    const float* Wgc  = (const float*)d_in[2];
    const float* bgc  = (const float*)d_in[3];
    const float* Wbi  = (const float*)d_in[4];
    const float* bbi  = (const float*)d_in[5];
    const float* aval = (const float*)d_in[6];
    const int*   arow = (const int*)d_in[7];
    const int*   acol = (const int*)d_in[8];
    const int*   users = (const int*)d_in[9];
    const int*   items = (const int*)d_in[10];

    int n_user = in_sizes[0] / D;
    int n_item = in_sizes[1] / D;
    int n = n_user + n_item;
    int E = in_sizes[6];
    int B = in_sizes[9];
    int L = in_sizes[3] / D;
    if (L > LMAX) L = LMAX;

    {
        int init_items = n * (D / 4);
        int hist_threads = (E + 3) / 4;
        int threads = init_items > hist_threads ? init_items : hist_threads;
        init_hist_kernel<<<(threads + 255) / 256, 256>>>(ue, ie, arow, n_user, n, E);
    }

    int nb = (n + 255) / 256;
    bsum_kernel<<<nb, 256>>>(n);
    bscan_kernel<<<1, NBMAX>>>(nb);
    rowptr_kernel<<<nb, 256>>>(n, E);
    scatter_kernel<<<(E / 4 + 255) / 256 + 1, 256>>>(aval, arow, acol, E);

    for (int k = 0; k < L; k++) {
        spmm_csr_kernel<<<(n + 63) / 64, 256>>>(n);
        dense_kernel<<<(n + 63) / 64, 256>>>(Wgc + k * D * D, bgc + k * D,
                                             Wbi + k * D * D, bbi + k * D,
                                             n, k, k < L - 1 ? 1 : 0);
    }

    {
        int total = 2 * B * ((LMAX + 1) * D / 4);
        gather_kernel<<<(total + 255) / 256, 256>>>(users, items, (float*)d_out, B, n_user);
    }
}